// round 6
// baseline (speedup 1.0000x reference)
#include <cuda_runtime.h>
#include <cuda_bf16.h>
#include <cuda_fp16.h>
#include <math.h>
#include <cstdint>

#define B_   2
#define S_   2048
#define D_   1024
#define H_   16
#define DH_  64
#define WIN_ 256
#define M_   (B_*S_)        // 4096
#define K2_  2048           // split-GEMM K (hi | 64*lo)

// ---------------------------------------------------------------------------
// Scratch (static device globals — no allocation)
// ---------------------------------------------------------------------------
__device__ __align__(16) __half g_qh[B_*H_*S_*DH_], g_ql[B_*H_*S_*DH_];
__device__ __align__(16) __half g_kh[B_*H_*S_*DH_], g_kl[B_*H_*S_*DH_];
__device__ __align__(16) __half g_vh[B_*H_*S_*DH_], g_vl[B_*H_*S_*DH_];
__device__ __align__(16) __half g_xs [(size_t)M_*K2_];   // x split [M,2048] = [hi | 64*lo]
__device__ __align__(16) __half g_ws [(size_t)3*D_*K2_]; // wq|wk|wv split [N,2048] = [64*hi | hi]
__device__ __align__(16) __half g_wos[(size_t)D_*K2_];   // wo split
__device__ __align__(16) __half g_aos[(size_t)M_*K2_];   // attn out split

// ---------------------------------------------------------------------------
// helpers
// ---------------------------------------------------------------------------
__device__ __forceinline__ uint32_t smem_u32(const void* p) {
    uint32_t a;
    asm("{ .reg .u64 t; cvta.to.shared.u64 t, %1; cvt.u32.u64 %0, t; }"
        : "=r"(a) : "l"(p));
    return a;
}

#define CP16(sm_addr, gptr) \
    asm volatile("cp.async.cg.shared.global [%0], [%1], 16;" \
                 :: "r"(sm_addr), "l"(gptr) : "memory")
#define CP_COMMIT() asm volatile("cp.async.commit_group;" ::: "memory")

#define LDSM4(r, addr) \
    asm volatile("ldmatrix.sync.aligned.m8n8.x4.shared.b16 {%0,%1,%2,%3}, [%4];" \
        : "=r"((r)[0]), "=r"((r)[1]), "=r"((r)[2]), "=r"((r)[3]) : "r"(addr))

#define LDSM4T(r, addr) \
    asm volatile("ldmatrix.sync.aligned.m8n8.x4.trans.shared.b16 {%0,%1,%2,%3}, [%4];" \
        : "=r"((r)[0]), "=r"((r)[1]), "=r"((r)[2]), "=r"((r)[3]) : "r"(addr))

#define MMAF16(c, a, b) \
    asm volatile("mma.sync.aligned.m16n8k16.row.col.f32.f16.f16.f32 " \
        "{%0,%1,%2,%3}, {%4,%5,%6,%7}, {%8,%9}, {%0,%1,%2,%3};" \
        : "+f"((c)[0]), "+f"((c)[1]), "+f"((c)[2]), "+f"((c)[3]) \
        : "r"((a)[0]), "r"((a)[1]), "r"((a)[2]), "r"((a)[3]), \
          "r"((b)[0]), "r"((b)[1]))

__device__ __forceinline__ uint32_t h2pack(float a, float b) {
    __half2 h = __floats2half2_rn(a, b);
    return *reinterpret_cast<uint32_t*>(&h);
}

// fp16 split: value -> (hi, 64*lo)   [GEMM operand layout]
__device__ __forceinline__ void split16(float f, unsigned short& h, unsigned short& l) {
    __half hb = __float2half_rn(f);
    float r = (f - __half2float(hb)) * 64.0f;
    __half lb = __float2half_rn(r);
    h = *reinterpret_cast<unsigned short*>(&hb);
    l = *reinterpret_cast<unsigned short*>(&lb);
}

// fp16 split: value -> (hi, lo) unscaled   [attention operand layout]
__device__ __forceinline__ void split16p(float f, unsigned short& h, unsigned short& l) {
    __half hb = __float2half_rn(f);
    __half lb = __float2half_rn(f - __half2float(hb));
    h = *reinterpret_cast<unsigned short*>(&hb);
    l = *reinterpret_cast<unsigned short*>(&lb);
}

// ---------------------------------------------------------------------------
// Prep: split x into [M,2048] = [hi | 64*lo]
// ---------------------------------------------------------------------------
__global__ __launch_bounds__(256) void split_x_kernel(
    const float4* __restrict__ x, unsigned short* __restrict__ out)
{
    int i = blockIdx.x * 256 + threadIdx.x;
    int r = i >> 8;
    int c = i & 255;
    float4 f = x[i];
    ushort4 h, l;
    split16(f.x, h.x, l.x);
    split16(f.y, h.y, l.y);
    split16(f.z, h.z, l.z);
    split16(f.w, h.w, l.w);
    size_t base = (size_t)r * K2_ + (c << 2);
    *(ushort4*)(out + base)        = h;
    *(ushort4*)(out + base + 1024) = l;
}

// ---------------------------------------------------------------------------
// Prep: transpose W [K,N] -> [N,2048] = [64*hi | hi]
// ---------------------------------------------------------------------------
__global__ __launch_bounds__(256) void split_w_t_kernel(
    const float* __restrict__ w, unsigned short* __restrict__ out)
{
    __shared__ float t[32][33];
    int tx = threadIdx.x, ty = threadIdx.y;
    int n0 = blockIdx.x * 32, k0 = blockIdx.y * 32;
#pragma unroll
    for (int j = 0; j < 32; j += 8)
        t[ty + j][tx] = w[(size_t)(k0 + ty + j) * D_ + n0 + tx];
    __syncthreads();
#pragma unroll
    for (int j = 0; j < 32; j += 8) {
        float f = t[tx][ty + j];
        __half h64 = __float2half_rn(f * 64.0f);
        __half h1  = __float2half_rn(f);
        size_t o = (size_t)(n0 + ty + j) * K2_ + k0 + tx;
        out[o]        = *reinterpret_cast<unsigned short*>(&h64);
        out[o + 1024] = *reinterpret_cast<unsigned short*>(&h1);
    }
}

// ---------------------------------------------------------------------------
// HMMA GEMM: C = A'[M,2048] @ B'[N,2048]^T = 64 * (A @ Bh^T)
// MODE 1: fused QKV; epilogue emits fp16 hi/lo pairs in [B,H,S,DH] layout.
// MODE 0: O projection, fp32 row-major store.
// ---------------------------------------------------------------------------
#define BK_      32
#define NITER_   (K2_ / BK_)       // 64
#define ROW_ST   80
#define A_BYTES  (128 * ROW_ST)
#define STG_SZ   (2 * A_BYTES)
#define GEMM_SMEM (4 * STG_SZ)

template<int MODE>
__global__ __launch_bounds__(256) void hgemm(
    const __half* __restrict__ A, const __half* __restrict__ Bw,
    const float* __restrict__ b0, const float* __restrict__ b1, const float* __restrict__ b2,
    float* __restrict__ fo,
    unsigned short* __restrict__ qh, unsigned short* __restrict__ ql,
    unsigned short* __restrict__ kh, unsigned short* __restrict__ kl,
    unsigned short* __restrict__ vh, unsigned short* __restrict__ vl)
{
    extern __shared__ char smc[];
    const uint32_t sb = smem_u32(smc);
    const int tid  = threadIdx.x;
    const int lane = tid & 31;
    const int wid  = tid >> 5;
    const int wm   = wid >> 2;
    const int wn   = wid & 3;
    const int bm   = blockIdx.y << 7;
    const int bn   = blockIdx.x << 7;

    const __half* Bp;
    const float* bias;
    unsigned short *Oh, *Ol;
    float scale;
    if (MODE == 1) {
        int z = blockIdx.z;
        Bp    = Bw + (size_t)z * D_ * K2_;
        bias  = (z == 0) ? b0 : (z == 1) ? b1 : b2;
        Oh    = (z == 0) ? qh : (z == 1) ? kh : vh;
        Ol    = (z == 0) ? ql : (z == 1) ? kl : vl;
        scale = (z == 0) ? 0.125f : 1.0f;
    } else {
        Bp = Bw; bias = b0; Oh = nullptr; Ol = nullptr; scale = 1.0f;
    }
    const float cscale = scale * 0.015625f;   // scale/64

    const int lr = tid >> 2;
    const int lc = (tid & 3) << 4;
    const int gc = (tid & 3) << 3;
    auto load_stage = [&](int i) {
        const uint32_t st = sb + (i & 3) * STG_SZ;
        const int k0 = i << 5;
#pragma unroll
        for (int h = 0; h < 2; h++) {
            int r = lr + (h << 6);
            CP16(st + r * ROW_ST + lc,           A  + (size_t)(bm + r) * K2_ + k0 + gc);
            CP16(st + A_BYTES + r * ROW_ST + lc, Bp + (size_t)(bn + r) * K2_ + k0 + gc);
        }
        CP_COMMIT();
    };

    load_stage(0); load_stage(1); load_stage(2);

    const int a_row  = lane & 15;
    const int a_koff = ((lane >> 4) << 3);
    const int b_row  = (lane & 7) + ((lane >> 4) << 3);
    const int b_koff = (((lane >> 3) & 1) << 3);
    const uint32_t aAddr = sb + (wm * 64 + a_row) * ROW_ST + a_koff * 2;
    const uint32_t bAddr = sb + A_BYTES + (wn * 32 + b_row) * ROW_ST + b_koff * 2;

    float c[4][4][4];
#pragma unroll
    for (int i = 0; i < 4; i++)
#pragma unroll
        for (int j = 0; j < 4; j++)
#pragma unroll
            for (int q = 0; q < 4; q++) c[i][j][q] = 0.f;

#pragma unroll 1
    for (int i = 0; i < NITER_; i++) {
        asm volatile("cp.async.wait_group 2;" ::: "memory");
        __syncthreads();
        const uint32_t so = (i & 3) * STG_SZ;
#pragma unroll
        for (int kk = 0; kk < 2; kk++) {
            uint32_t a[4][4], b[4][2];
#pragma unroll
            for (int mt = 0; mt < 4; mt++)
                LDSM4(a[mt], aAddr + so + mt * (16 * ROW_ST) + kk * 32);
#pragma unroll
            for (int np = 0; np < 2; np++) {
                uint32_t r[4];
                LDSM4(r, bAddr + so + np * (16 * ROW_ST) + kk * 32);
                b[np * 2][0] = r[0]; b[np * 2][1] = r[1];
                b[np * 2 + 1][0] = r[2]; b[np * 2 + 1][1] = r[3];
            }
#pragma unroll
            for (int mt = 0; mt < 4; mt++)
#pragma unroll
                for (int nt = 0; nt < 4; nt++)
                    MMAF16(c[mt][nt], a[mt], b[nt]);
        }
        if (i + 3 < NITER_) load_stage(i + 3);
        else                CP_COMMIT();
    }

    const int row0 = bm + wm * 64 + (lane >> 2);
    const int col0 = bn + wn * 32 + ((lane & 3) << 1);
#pragma unroll
    for (int mt = 0; mt < 4; mt++) {
#pragma unroll
        for (int nt = 0; nt < 4; nt++) {
            int gn = col0 + nt * 8;
            float bx = bias[gn] * scale, by = bias[gn + 1] * scale;
#pragma unroll
            for (int half = 0; half < 2; half++) {
                int gm = row0 + mt * 16 + half * 8;
                float ox = c[mt][nt][half * 2 + 0] * cscale + bx;
                float oy = c[mt][nt][half * 2 + 1] * cscale + by;
                if (MODE == 0) {
                    float2 o = make_float2(ox, oy);
                    *(float2*)(fo + (size_t)gm * D_ + gn) = o;
                } else {
                    int bb = gm >> 11, ss = gm & (S_ - 1);
                    int hh = gn >> 6,  dd = gn & (DH_ - 1);
                    unsigned short h0, l0, h1, l1;
                    split16p(ox, h0, l0);
                    split16p(oy, h1, l1);
                    size_t addr = ((((size_t)bb * H_ + hh) * S_ + ss) << 6) + dd;
                    *(uint32_t*)(Oh + addr) = ((uint32_t)h1 << 16) | h0;
                    *(uint32_t*)(Ol + addr) = ((uint32_t)l1 << 16) | l0;
                }
            }
        }
    }
}

// ---------------------------------------------------------------------------
// HMMA windowed attention v2: fp16 hi/lo inputs staged via cp.async,
// 3-buffer K/V ring (prefetch depth 2, one __syncthreads per chunk),
// per-warp skip of fully-masked chunks.
// block = (128 q-rows, head, batch), 8 warps, warp = 16 q-rows x 64-key chunk.
// ---------------------------------------------------------------------------
#define AROW    72                     // halfs per smem row (144 B)
#define QT_     128
#define QBYTES  (2 * 128 * AROW * 2)   // Qh+Ql: 36864
#define KVSTG   (4 * 64 * AROW * 2)    // Kh,Kl,Vh,Vl: 36864
#define ATT_SMEM (QBYTES + 3 * KVSTG)  // 147456

__global__ __launch_bounds__(256) void attn_mma(
    const __half* __restrict__ Qh_g, const __half* __restrict__ Ql_g,
    const __half* __restrict__ Kh_g, const __half* __restrict__ Kl_g,
    const __half* __restrict__ Vh_g, const __half* __restrict__ Vl_g,
    unsigned short* __restrict__ Osplit)
{
    extern __shared__ char sma[];
    const uint32_t sQ  = smem_u32(sma);
    const uint32_t sKV = sQ + QBYTES;

    const int tid  = threadIdx.x;
    const int lane = tid & 31;
    const int w    = tid >> 5;
    const int q0t  = blockIdx.x << 7;
    const int h    = blockIdx.y;
    const int b    = blockIdx.z;
    const size_t bh = ((size_t)b * H_ + h) * S_;

    const int kstart = (q0t - WIN_) > 0 ? (q0t - WIN_) : 0;
    const int nch    = ((q0t + 64) - kstart) / 64 + 1;

    // ---- loaders (cp.async, 8 chunks of 16B per thread each) ----
    auto load_q = [&]() {
        const __half* srcs[2] = { Qh_g + (bh + q0t) * DH_, Ql_g + (bh + q0t) * DH_ };
#pragma unroll
        for (int it = 0; it < 8; it++) {
            int i = it * 256 + tid;
            int arr = i >> 10, rem = i & 1023;
            int row = rem >> 3, c = rem & 7;
            CP16(sQ + arr * (128 * AROW * 2) + row * (AROW * 2) + c * 16,
                 srcs[arr] + (row << 6) + (c << 3));
        }
    };
    auto load_kv = [&](int kb, int buf) {
        const __half* srcs[4] = { Kh_g + (bh + kb) * DH_, Kl_g + (bh + kb) * DH_,
                                  Vh_g + (bh + kb) * DH_, Vl_g + (bh + kb) * DH_ };
        const uint32_t base = sKV + buf * KVSTG;
#pragma unroll
        for (int it = 0; it < 8; it++) {
            int i = it * 256 + tid;
            int arr = i >> 9, rem = i & 511;
            int row = rem >> 3, c = rem & 7;
            CP16(base + arr * (64 * AROW * 2) + row * (AROW * 2) + c * 16,
                 srcs[arr] + (row << 6) + (c << 3));
        }
    };

    // prologue: group0 = Q + KV chunk 0; group1 = KV chunk 1
    load_q();
    load_kv(kstart, 0);
    CP_COMMIT();
    if (nch > 1) { load_kv(kstart + 64, 1); CP_COMMIT(); }

    // ldmatrix lane offsets
    const uint32_t aOff  = (w * 16 + (lane & 15)) * (AROW * 2) + ((lane >> 4) << 4);
    const uint32_t bKOff = ((lane & 7) + ((lane >> 4) << 3)) * (AROW * 2)
                         + (((lane >> 3) & 1) << 4);
    const uint32_t bVOff = ((lane & 7) + (((lane >> 3) & 1) << 3)) * (AROW * 2)
                         + ((lane >> 4) << 4);
    const uint32_t sQh = sQ, sQl = sQ + 128 * AROW * 2;

    float m2[2] = {-1e30f, -1e30f};
    float l2[2] = {0.f, 0.f};
    float co[8][4];
#pragma unroll
    for (int i = 0; i < 8; i++)
#pragma unroll
        for (int j = 0; j < 4; j++) co[i][j] = 0.f;

    const int baserow = q0t + w * 16 + (lane >> 2);
    const int jc0     = (lane & 3) << 1;
    const int qmin    = q0t + w * 16;

#pragma unroll 1
    for (int ci = 0; ci < nch; ci++) {
        const int kb = kstart + ci * 64;
        if (ci + 1 < nch) asm volatile("cp.async.wait_group 1;" ::: "memory");
        else              asm volatile("cp.async.wait_group 0;" ::: "memory");
        __syncthreads();
        if (ci + 2 < nch) { load_kv(kstart + (ci + 2) * 64, (ci + 2) % 3); CP_COMMIT(); }

        // per-warp skip of fully-masked chunks
        if (kb > qmin + 15 || kb + 63 < qmin - WIN_) continue;

        const uint32_t kvb = sKV + (ci % 3) * KVSTG;
        const uint32_t sKh = kvb;
        const uint32_t sKl = kvb + (64 * AROW * 2);
        const uint32_t sVh = kvb + 2 * (64 * AROW * 2);
        const uint32_t sVl = kvb + 3 * (64 * AROW * 2);

        // ---- scores: 3-term fp16 split ----
        float s[8][4];
#pragma unroll
        for (int i = 0; i < 8; i++)
#pragma unroll
            for (int j = 0; j < 4; j++) s[i][j] = 0.f;

#pragma unroll
        for (int ks = 0; ks < 4; ks++) {
            uint32_t aH[4], aL[4];
            LDSM4(aH, sQh + aOff + ks * 32);
            LDSM4(aL, sQl + aOff + ks * 32);
#pragma unroll
            for (int np = 0; np < 4; np++) {
                uint32_t bH[4], bL[4];
                LDSM4(bH, sKh + bKOff + np * (16 * AROW * 2) + ks * 32);
                LDSM4(bL, sKl + bKOff + np * (16 * AROW * 2) + ks * 32);
                MMAF16(s[np * 2],     aH, bH);
                MMAF16(s[np * 2],     aL, bH);
                MMAF16(s[np * 2],     aH, bL);
                MMAF16(s[np * 2 + 1], aH, bH + 2);
                MMAF16(s[np * 2 + 1], aL, bH + 2);
                MMAF16(s[np * 2 + 1], aH, bL + 2);
            }
        }

        // ---- mask + online softmax ----
#pragma unroll
        for (int rh = 0; rh < 2; rh++) {
            int qi = baserow + rh * 8;
            float mx = -1e30f;
#pragma unroll
            for (int nt = 0; nt < 8; nt++) {
#pragma unroll
                for (int j = 0; j < 2; j++) {
                    int kj = kb + nt * 8 + jc0 + j;
                    float& v = s[nt][rh * 2 + j];
                    if (kj > qi || (qi - kj) > WIN_) v = -1e30f;
                    mx = fmaxf(mx, v);
                }
            }
            mx = fmaxf(mx, __shfl_xor_sync(0xffffffffu, mx, 1));
            mx = fmaxf(mx, __shfl_xor_sync(0xffffffffu, mx, 2));
            float mn   = fmaxf(m2[rh], mx);
            float corr = __expf(m2[rh] - mn);
            m2[rh] = mn;
            float ps = 0.f;
#pragma unroll
            for (int nt = 0; nt < 8; nt++) {
#pragma unroll
                for (int j = 0; j < 2; j++) {
                    float p = __expf(s[nt][rh * 2 + j] - mn);
                    s[nt][rh * 2 + j] = p;
                    ps += p;
                }
            }
            ps += __shfl_xor_sync(0xffffffffu, ps, 1);
            ps += __shfl_xor_sync(0xffffffffu, ps, 2);
            l2[rh] = l2[rh] * corr + ps;
#pragma unroll
            for (int nt = 0; nt < 8; nt++) {
                co[nt][rh * 2]     *= corr;
                co[nt][rh * 2 + 1] *= corr;
            }
        }

        // ---- P -> fp16 hi/lo A-frags ----
        uint32_t ph[8][2], pl[8][2];
#pragma unroll
        for (int nt = 0; nt < 8; nt++) {
            __half h0 = __float2half_rn(s[nt][0]), h1 = __float2half_rn(s[nt][1]);
            __half h2 = __float2half_rn(s[nt][2]), h3 = __float2half_rn(s[nt][3]);
            __half2 p01 = __halves2half2(h0, h1), p23 = __halves2half2(h2, h3);
            ph[nt][0] = *reinterpret_cast<uint32_t*>(&p01);
            ph[nt][1] = *reinterpret_cast<uint32_t*>(&p23);
            pl[nt][0] = h2pack(s[nt][0] - __half2float(h0), s[nt][1] - __half2float(h1));
            pl[nt][1] = h2pack(s[nt][2] - __half2float(h2), s[nt][3] - __half2float(h3));
        }

        // ---- PV: co += Ph*Vh + Pl*Vh + Ph*Vl ----
#pragma unroll
        for (int ks = 0; ks < 4; ks++) {
            uint32_t aPh[4] = { ph[2*ks][0], ph[2*ks][1], ph[2*ks+1][0], ph[2*ks+1][1] };
            uint32_t aPl[4] = { pl[2*ks][0], pl[2*ks][1], pl[2*ks+1][0], pl[2*ks+1][1] };
#pragma unroll
            for (int np = 0; np < 4; np++) {
                uint32_t vH[4], vL[4];
                LDSM4T(vH, sVh + bVOff + ks * (16 * AROW * 2) + np * 32);
                LDSM4T(vL, sVl + bVOff + ks * (16 * AROW * 2) + np * 32);
                MMAF16(co[np * 2],     aPh, vH);
                MMAF16(co[np * 2],     aPl, vH);
                MMAF16(co[np * 2],     aPh, vL);
                MMAF16(co[np * 2 + 1], aPh, vH + 2);
                MMAF16(co[np * 2 + 1], aPl, vH + 2);
                MMAF16(co[np * 2 + 1], aPh, vL + 2);
            }
        }
    }

    // ---- normalize + fp16 [hi | 64*lo] split store for O projection ----
    const int ocol0 = (h << 6) + jc0;
#pragma unroll
    for (int rh = 0; rh < 2; rh++) {
        float inv = 1.f / l2[rh];
        size_t rbase = (size_t)(b * S_ + baserow + rh * 8) * K2_;
#pragma unroll
        for (int nt = 0; nt < 8; nt++) {
            float v0 = co[nt][rh * 2]     * inv;
            float v1 = co[nt][rh * 2 + 1] * inv;
            unsigned short h0, l0, h1, l1;
            split16(v0, h0, l0);
            split16(v1, h1, l1);
            size_t p = rbase + ocol0 + nt * 8;
            *(uint32_t*)(Osplit + p)        = ((uint32_t)h1 << 16) | h0;
            *(uint32_t*)(Osplit + p + 1024) = ((uint32_t)l1 << 16) | l0;
        }
    }
}

// ---------------------------------------------------------------------------
extern "C" void kernel_launch(void* const* d_in, const int* in_sizes, int n_in,
                              void* d_out, int out_size)
{
    const float* x  = (const float*)d_in[0];
    const float* wq = (const float*)d_in[1];
    const float* bq = (const float*)d_in[2];
    const float* wk = (const float*)d_in[3];
    const float* bk = (const float*)d_in[4];
    const float* wv = (const float*)d_in[5];
    const float* bv = (const float*)d_in[6];
    const float* wo = (const float*)d_in[7];
    const float* bo = (const float*)d_in[8];
    float* out = (float*)d_out;

    __half *qh, *ql, *kh, *kl, *vh, *vl;
    unsigned short *xs, *ws, *wos, *aos;
    cudaGetSymbolAddress((void**)&qh,  g_qh);  cudaGetSymbolAddress((void**)&ql,  g_ql);
    cudaGetSymbolAddress((void**)&kh,  g_kh);  cudaGetSymbolAddress((void**)&kl,  g_kl);
    cudaGetSymbolAddress((void**)&vh,  g_vh);  cudaGetSymbolAddress((void**)&vl,  g_vl);
    cudaGetSymbolAddress((void**)&xs,  g_xs);
    cudaGetSymbolAddress((void**)&ws,  g_ws);
    cudaGetSymbolAddress((void**)&wos, g_wos);
    cudaGetSymbolAddress((void**)&aos, g_aos);

    cudaFuncSetAttribute(hgemm<0>, cudaFuncAttributeMaxDynamicSharedMemorySize, GEMM_SMEM);
    cudaFuncSetAttribute(hgemm<1>, cudaFuncAttributeMaxDynamicSharedMemorySize, GEMM_SMEM);
    cudaFuncSetAttribute(attn_mma, cudaFuncAttributeMaxDynamicSharedMemorySize, ATT_SMEM);

    // Prep: operand splits
    split_x_kernel<<<(M_ * D_) / (256 * 4), 256>>>((const float4*)x, xs);
    dim3 tg(32, 32), tb(32, 8);
    split_w_t_kernel<<<tg, tb>>>(wq, ws);
    split_w_t_kernel<<<tg, tb>>>(wk, ws + (size_t)D_ * K2_);
    split_w_t_kernel<<<tg, tb>>>(wv, ws + (size_t)2 * D_ * K2_);
    split_w_t_kernel<<<tg, tb>>>(wo, wos);

    // Fused QKV projections -> fp16 hi/lo [B,H,S,DH] (1/sqrt(DH) folded into Q)
    dim3 gq(D_ / 128, M_ / 128, 3);
    hgemm<1><<<gq, 256, GEMM_SMEM>>>(
        (const __half*)xs, (const __half*)ws,
        bq, bk, bv, nullptr,
        (unsigned short*)qh, (unsigned short*)ql,
        (unsigned short*)kh, (unsigned short*)kl,
        (unsigned short*)vh, (unsigned short*)vl);

    // Attention (HMMA, cp.async ring)
    attn_mma<<<dim3(S_ / QT_, H_, B_), 256, ATT_SMEM>>>(
        qh, ql, kh, kl, vh, vl, aos);

    // Output projection
    dim3 go(D_ / 128, M_ / 128, 1);
    hgemm<0><<<go, 256, GEMM_SMEM>>>(
        (const __half*)aos, (const __half*)wos,
        bo, bo, bo, out,
        nullptr, nullptr, nullptr, nullptr, nullptr, nullptr);
}

// round 7
// speedup vs baseline: 1.0025x; 1.0025x over previous
#include <cuda_runtime.h>
#include <cuda_bf16.h>
#include <cuda_fp16.h>
#include <math.h>
#include <cstdint>

#define B_   2
#define S_   2048
#define D_   1024
#define H_   16
#define DH_  64
#define WIN_ 256
#define M_   (B_*S_)        // 4096
#define K2_  2048           // split-GEMM K (hi | 64*lo)

// ---------------------------------------------------------------------------
// Scratch (static device globals — no allocation)
// ---------------------------------------------------------------------------
__device__ __align__(16) __half g_qh[B_*H_*S_*DH_], g_ql[B_*H_*S_*DH_];
__device__ __align__(16) __half g_kh[B_*H_*S_*DH_], g_kl[B_*H_*S_*DH_];
__device__ __align__(16) __half g_vh[B_*H_*S_*DH_], g_vl[B_*H_*S_*DH_];
__device__ __align__(16) __half g_xs [(size_t)M_*K2_];   // x split [M,2048] = [hi | 64*lo]
__device__ __align__(16) __half g_ws [(size_t)3*D_*K2_]; // wq|wk|wv split [N,2048] = [64*hi | hi]
__device__ __align__(16) __half g_wos[(size_t)D_*K2_];   // wo split
__device__ __align__(16) __half g_aos[(size_t)M_*K2_];   // attn out split

// ---------------------------------------------------------------------------
// helpers
// ---------------------------------------------------------------------------
__device__ __forceinline__ uint32_t smem_u32(const void* p) {
    uint32_t a;
    asm("{ .reg .u64 t; cvta.to.shared.u64 t, %1; cvt.u32.u64 %0, t; }"
        : "=r"(a) : "l"(p));
    return a;
}

#define CP16(sm_addr, gptr) \
    asm volatile("cp.async.cg.shared.global [%0], [%1], 16;" \
                 :: "r"(sm_addr), "l"(gptr) : "memory")
#define CP_COMMIT() asm volatile("cp.async.commit_group;" ::: "memory")

#define LDSM4(r, addr) \
    asm volatile("ldmatrix.sync.aligned.m8n8.x4.shared.b16 {%0,%1,%2,%3}, [%4];" \
        : "=r"((r)[0]), "=r"((r)[1]), "=r"((r)[2]), "=r"((r)[3]) : "r"(addr))

#define LDSM4T(r, addr) \
    asm volatile("ldmatrix.sync.aligned.m8n8.x4.trans.shared.b16 {%0,%1,%2,%3}, [%4];" \
        : "=r"((r)[0]), "=r"((r)[1]), "=r"((r)[2]), "=r"((r)[3]) : "r"(addr))

#define MMAF16(c, a, b) \
    asm volatile("mma.sync.aligned.m16n8k16.row.col.f32.f16.f16.f32 " \
        "{%0,%1,%2,%3}, {%4,%5,%6,%7}, {%8,%9}, {%0,%1,%2,%3};" \
        : "+f"((c)[0]), "+f"((c)[1]), "+f"((c)[2]), "+f"((c)[3]) \
        : "r"((a)[0]), "r"((a)[1]), "r"((a)[2]), "r"((a)[3]), \
          "r"((b)[0]), "r"((b)[1]))

__device__ __forceinline__ uint32_t h2pack(float a, float b) {
    __half2 h = __floats2half2_rn(a, b);
    return *reinterpret_cast<uint32_t*>(&h);
}

// fp16 split: value -> (hi, 64*lo)   [GEMM operand layout]
__device__ __forceinline__ void split16(float f, unsigned short& h, unsigned short& l) {
    __half hb = __float2half_rn(f);
    float r = (f - __half2float(hb)) * 64.0f;
    __half lb = __float2half_rn(r);
    h = *reinterpret_cast<unsigned short*>(&hb);
    l = *reinterpret_cast<unsigned short*>(&lb);
}

// fp16 split: value -> (hi, lo) unscaled   [attention operand layout]
__device__ __forceinline__ void split16p(float f, unsigned short& h, unsigned short& l) {
    __half hb = __float2half_rn(f);
    __half lb = __float2half_rn(f - __half2float(hb));
    h = *reinterpret_cast<unsigned short*>(&hb);
    l = *reinterpret_cast<unsigned short*>(&lb);
}

// ---------------------------------------------------------------------------
// Prep: split x into [M,2048] = [hi | 64*lo]
// ---------------------------------------------------------------------------
__global__ __launch_bounds__(256) void split_x_kernel(
    const float4* __restrict__ x, unsigned short* __restrict__ out)
{
    int i = blockIdx.x * 256 + threadIdx.x;
    int r = i >> 8;
    int c = i & 255;
    float4 f = x[i];
    ushort4 h, l;
    split16(f.x, h.x, l.x);
    split16(f.y, h.y, l.y);
    split16(f.z, h.z, l.z);
    split16(f.w, h.w, l.w);
    size_t base = (size_t)r * K2_ + (c << 2);
    *(ushort4*)(out + base)        = h;
    *(ushort4*)(out + base + 1024) = l;
}

// ---------------------------------------------------------------------------
// Prep: transpose 4 weight mats [K,N] -> [N,2048] = [64*hi | hi] in ONE launch
// blockIdx.z selects the weight (0=wq,1=wk,2=wv,3=wo).
// ---------------------------------------------------------------------------
__global__ __launch_bounds__(256) void split_w4_kernel(
    const float* __restrict__ wq, const float* __restrict__ wk,
    const float* __restrict__ wv, const float* __restrict__ wo,
    unsigned short* __restrict__ ws, unsigned short* __restrict__ wos)
{
    const int z = blockIdx.z;
    const float* w = (z == 0) ? wq : (z == 1) ? wk : (z == 2) ? wv : wo;
    unsigned short* out = (z == 3) ? wos : ws + (size_t)z * D_ * K2_;

    __shared__ float t[32][33];
    int tx = threadIdx.x, ty = threadIdx.y;
    int n0 = blockIdx.x * 32, k0 = blockIdx.y * 32;
#pragma unroll
    for (int j = 0; j < 32; j += 8)
        t[ty + j][tx] = w[(size_t)(k0 + ty + j) * D_ + n0 + tx];
    __syncthreads();
#pragma unroll
    for (int j = 0; j < 32; j += 8) {
        float f = t[tx][ty + j];
        __half h64 = __float2half_rn(f * 64.0f);
        __half h1  = __float2half_rn(f);
        size_t o = (size_t)(n0 + ty + j) * K2_ + k0 + tx;
        out[o]        = *reinterpret_cast<unsigned short*>(&h64);
        out[o + 1024] = *reinterpret_cast<unsigned short*>(&h1);
    }
}

// ---------------------------------------------------------------------------
// HMMA GEMM: C = A'[M,2048] @ B'[N,2048]^T = 64 * (A @ Bh^T)
// CTA tile 256x128, BK=32, 4-stage cp.async pipeline.
// 8 warps (4x2), warp tile 64x64 (32 MMA : 8 LDSM per kk -> high tensor feed).
// MODE 1: fused QKV; epilogue emits fp16 hi/lo pairs in [B,H,S,DH] layout.
// MODE 0: O projection, fp32 row-major store.
// ---------------------------------------------------------------------------
#define BK_      32
#define NITER_   (K2_ / BK_)        // 64
#define ROW_ST   80
#define A_BYTES2 (256 * ROW_ST)     // 20480
#define B_BYTES2 (128 * ROW_ST)     // 10240
#define STG2     (A_BYTES2 + B_BYTES2)   // 30720
#define GEMM_SMEM (4 * STG2)        // 122880

template<int MODE>
__global__ __launch_bounds__(256) void hgemm(
    const __half* __restrict__ A, const __half* __restrict__ Bw,
    const float* __restrict__ b0, const float* __restrict__ b1, const float* __restrict__ b2,
    float* __restrict__ fo,
    unsigned short* __restrict__ qh, unsigned short* __restrict__ ql,
    unsigned short* __restrict__ kh, unsigned short* __restrict__ kl,
    unsigned short* __restrict__ vh, unsigned short* __restrict__ vl)
{
    extern __shared__ char smc[];
    const uint32_t sb = smem_u32(smc);
    const int tid  = threadIdx.x;
    const int lane = tid & 31;
    const int wid  = tid >> 5;
    const int wm   = wid >> 1;      // 0..3
    const int wn   = wid & 1;       // 0..1
    const int bm   = blockIdx.y << 8;   // 256-row tiles
    const int bn   = blockIdx.x << 7;   // 128-col tiles

    const __half* Bp;
    const float* bias;
    unsigned short *Oh, *Ol;
    float scale;
    if (MODE == 1) {
        int z = blockIdx.z;
        Bp    = Bw + (size_t)z * D_ * K2_;
        bias  = (z == 0) ? b0 : (z == 1) ? b1 : b2;
        Oh    = (z == 0) ? qh : (z == 1) ? kh : vh;
        Ol    = (z == 0) ? ql : (z == 1) ? kl : vl;
        scale = (z == 0) ? 0.125f : 1.0f;
    } else {
        Bp = Bw; bias = b0; Oh = nullptr; Ol = nullptr; scale = 1.0f;
    }
    const float cscale = scale * 0.015625f;   // scale/64

    const int lr = tid >> 2;        // 0..63
    const int lc = (tid & 3) << 4;  // byte col within row
    const int gc = (tid & 3) << 3;  // half col
    auto load_stage = [&](int i) {
        const uint32_t st = sb + (i & 3) * STG2;
        const int k0 = i << 5;
#pragma unroll
        for (int h = 0; h < 4; h++) {               // A: 256 rows
            int r = lr + (h << 6);
            CP16(st + r * ROW_ST + lc, A + (size_t)(bm + r) * K2_ + k0 + gc);
        }
#pragma unroll
        for (int h = 0; h < 2; h++) {               // B: 128 rows
            int r = lr + (h << 6);
            CP16(st + A_BYTES2 + r * ROW_ST + lc, Bp + (size_t)(bn + r) * K2_ + k0 + gc);
        }
        CP_COMMIT();
    };

    load_stage(0); load_stage(1); load_stage(2);

    const int a_row  = lane & 15;
    const int a_koff = ((lane >> 4) << 3);
    const int b_row  = (lane & 7) + ((lane >> 4) << 3);
    const int b_koff = (((lane >> 3) & 1) << 3);
    const uint32_t aAddr = sb + (wm * 64 + a_row) * ROW_ST + a_koff * 2;
    const uint32_t bAddr = sb + A_BYTES2 + (wn * 64 + b_row) * ROW_ST + b_koff * 2;

    float c[4][8][4];
#pragma unroll
    for (int i = 0; i < 4; i++)
#pragma unroll
        for (int j = 0; j < 8; j++)
#pragma unroll
            for (int q = 0; q < 4; q++) c[i][j][q] = 0.f;

#pragma unroll 1
    for (int i = 0; i < NITER_; i++) {
        asm volatile("cp.async.wait_group 2;" ::: "memory");
        __syncthreads();
        const uint32_t so = (i & 3) * STG2;
#pragma unroll
        for (int kk = 0; kk < 2; kk++) {
            uint32_t a[4][4], b[8][2];
#pragma unroll
            for (int mt = 0; mt < 4; mt++)
                LDSM4(a[mt], aAddr + so + mt * (16 * ROW_ST) + kk * 32);
#pragma unroll
            for (int np = 0; np < 4; np++) {
                uint32_t r[4];
                LDSM4(r, bAddr + so + np * (16 * ROW_ST) + kk * 32);
                b[np * 2][0] = r[0]; b[np * 2][1] = r[1];
                b[np * 2 + 1][0] = r[2]; b[np * 2 + 1][1] = r[3];
            }
#pragma unroll
            for (int mt = 0; mt < 4; mt++)
#pragma unroll
                for (int nt = 0; nt < 8; nt++)
                    MMAF16(c[mt][nt], a[mt], b[nt]);
        }
        if (i + 3 < NITER_) load_stage(i + 3);
        else                CP_COMMIT();
    }

    const int row0 = bm + wm * 64 + (lane >> 2);
    const int col0 = bn + wn * 64 + ((lane & 3) << 1);
#pragma unroll
    for (int mt = 0; mt < 4; mt++) {
#pragma unroll
        for (int nt = 0; nt < 8; nt++) {
            int gn = col0 + nt * 8;
            float bx = bias[gn] * scale, by = bias[gn + 1] * scale;
#pragma unroll
            for (int half = 0; half < 2; half++) {
                int gm = row0 + mt * 16 + half * 8;
                float ox = c[mt][nt][half * 2 + 0] * cscale + bx;
                float oy = c[mt][nt][half * 2 + 1] * cscale + by;
                if (MODE == 0) {
                    float2 o = make_float2(ox, oy);
                    *(float2*)(fo + (size_t)gm * D_ + gn) = o;
                } else {
                    int bb = gm >> 11, ss = gm & (S_ - 1);
                    int hh = gn >> 6,  dd = gn & (DH_ - 1);
                    unsigned short h0, l0, h1, l1;
                    split16p(ox, h0, l0);
                    split16p(oy, h1, l1);
                    size_t addr = ((((size_t)bb * H_ + hh) * S_ + ss) << 6) + dd;
                    *(uint32_t*)(Oh + addr) = ((uint32_t)h1 << 16) | h0;
                    *(uint32_t*)(Ol + addr) = ((uint32_t)l1 << 16) | l0;
                }
            }
        }
    }
}

// ---------------------------------------------------------------------------
// HMMA windowed attention: fp16 hi/lo inputs staged via cp.async,
// 3-buffer K/V ring, per-warp skip of fully-masked chunks.
// block = (128 q-rows, head, batch), 8 warps, warp = 16 q-rows x 64-key chunk.
// ---------------------------------------------------------------------------
#define AROW    72                     // halfs per smem row (144 B)
#define QT_     128
#define QBYTES  (2 * 128 * AROW * 2)   // Qh+Ql: 36864
#define KVSTG   (4 * 64 * AROW * 2)    // Kh,Kl,Vh,Vl: 36864
#define ATT_SMEM (QBYTES + 3 * KVSTG)  // 147456

__global__ __launch_bounds__(256) void attn_mma(
    const __half* __restrict__ Qh_g, const __half* __restrict__ Ql_g,
    const __half* __restrict__ Kh_g, const __half* __restrict__ Kl_g,
    const __half* __restrict__ Vh_g, const __half* __restrict__ Vl_g,
    unsigned short* __restrict__ Osplit)
{
    extern __shared__ char sma[];
    const uint32_t sQ  = smem_u32(sma);
    const uint32_t sKV = sQ + QBYTES;

    const int tid  = threadIdx.x;
    const int lane = tid & 31;
    const int w    = tid >> 5;
    const int q0t  = blockIdx.x << 7;
    const int h    = blockIdx.y;
    const int b    = blockIdx.z;
    const size_t bh = ((size_t)b * H_ + h) * S_;

    const int kstart = (q0t - WIN_) > 0 ? (q0t - WIN_) : 0;
    const int nch    = ((q0t + 64) - kstart) / 64 + 1;

    auto load_q = [&]() {
        const __half* srcs[2] = { Qh_g + (bh + q0t) * DH_, Ql_g + (bh + q0t) * DH_ };
#pragma unroll
        for (int it = 0; it < 8; it++) {
            int i = it * 256 + tid;
            int arr = i >> 10, rem = i & 1023;
            int row = rem >> 3, c = rem & 7;
            CP16(sQ + arr * (128 * AROW * 2) + row * (AROW * 2) + c * 16,
                 srcs[arr] + (row << 6) + (c << 3));
        }
    };
    auto load_kv = [&](int kb, int buf) {
        const __half* srcs[4] = { Kh_g + (bh + kb) * DH_, Kl_g + (bh + kb) * DH_,
                                  Vh_g + (bh + kb) * DH_, Vl_g + (bh + kb) * DH_ };
        const uint32_t base = sKV + buf * KVSTG;
#pragma unroll
        for (int it = 0; it < 8; it++) {
            int i = it * 256 + tid;
            int arr = i >> 9, rem = i & 511;
            int row = rem >> 3, c = rem & 7;
            CP16(base + arr * (64 * AROW * 2) + row * (AROW * 2) + c * 16,
                 srcs[arr] + (row << 6) + (c << 3));
        }
    };

    load_q();
    load_kv(kstart, 0);
    CP_COMMIT();
    if (nch > 1) { load_kv(kstart + 64, 1); CP_COMMIT(); }

    const uint32_t aOff  = (w * 16 + (lane & 15)) * (AROW * 2) + ((lane >> 4) << 4);
    const uint32_t bKOff = ((lane & 7) + ((lane >> 4) << 3)) * (AROW * 2)
                         + (((lane >> 3) & 1) << 4);
    const uint32_t bVOff = ((lane & 7) + (((lane >> 3) & 1) << 3)) * (AROW * 2)
                         + ((lane >> 4) << 4);
    const uint32_t sQh = sQ, sQl = sQ + 128 * AROW * 2;

    float m2[2] = {-1e30f, -1e30f};
    float l2[2] = {0.f, 0.f};
    float co[8][4];
#pragma unroll
    for (int i = 0; i < 8; i++)
#pragma unroll
        for (int j = 0; j < 4; j++) co[i][j] = 0.f;

    const int baserow = q0t + w * 16 + (lane >> 2);
    const int jc0     = (lane & 3) << 1;
    const int qmin    = q0t + w * 16;

#pragma unroll 1
    for (int ci = 0; ci < nch; ci++) {
        const int kb = kstart + ci * 64;
        if (ci + 1 < nch) asm volatile("cp.async.wait_group 1;" ::: "memory");
        else              asm volatile("cp.async.wait_group 0;" ::: "memory");
        __syncthreads();
        if (ci + 2 < nch) { load_kv(kstart + (ci + 2) * 64, (ci + 2) % 3); CP_COMMIT(); }

        if (kb > qmin + 15 || kb + 63 < qmin - WIN_) continue;

        const uint32_t kvb = sKV + (ci % 3) * KVSTG;
        const uint32_t sKh = kvb;
        const uint32_t sKl = kvb + (64 * AROW * 2);
        const uint32_t sVh = kvb + 2 * (64 * AROW * 2);
        const uint32_t sVl = kvb + 3 * (64 * AROW * 2);

        float s[8][4];
#pragma unroll
        for (int i = 0; i < 8; i++)
#pragma unroll
            for (int j = 0; j < 4; j++) s[i][j] = 0.f;

#pragma unroll
        for (int ks = 0; ks < 4; ks++) {
            uint32_t aH[4], aL[4];
            LDSM4(aH, sQh + aOff + ks * 32);
            LDSM4(aL, sQl + aOff + ks * 32);
#pragma unroll
            for (int np = 0; np < 4; np++) {
                uint32_t bH[4], bL[4];
                LDSM4(bH, sKh + bKOff + np * (16 * AROW * 2) + ks * 32);
                LDSM4(bL, sKl + bKOff + np * (16 * AROW * 2) + ks * 32);
                MMAF16(s[np * 2],     aH, bH);
                MMAF16(s[np * 2],     aL, bH);
                MMAF16(s[np * 2],     aH, bL);
                MMAF16(s[np * 2 + 1], aH, bH + 2);
                MMAF16(s[np * 2 + 1], aL, bH + 2);
                MMAF16(s[np * 2 + 1], aH, bL + 2);
            }
        }

#pragma unroll
        for (int rh = 0; rh < 2; rh++) {
            int qi = baserow + rh * 8;
            float mx = -1e30f;
#pragma unroll
            for (int nt = 0; nt < 8; nt++) {
#pragma unroll
                for (int j = 0; j < 2; j++) {
                    int kj = kb + nt * 8 + jc0 + j;
                    float& v = s[nt][rh * 2 + j];
                    if (kj > qi || (qi - kj) > WIN_) v = -1e30f;
                    mx = fmaxf(mx, v);
                }
            }
            mx = fmaxf(mx, __shfl_xor_sync(0xffffffffu, mx, 1));
            mx = fmaxf(mx, __shfl_xor_sync(0xffffffffu, mx, 2));
            float mn   = fmaxf(m2[rh], mx);
            float corr = __expf(m2[rh] - mn);
            m2[rh] = mn;
            float ps = 0.f;
#pragma unroll
            for (int nt = 0; nt < 8; nt++) {
#pragma unroll
                for (int j = 0; j < 2; j++) {
                    float p = __expf(s[nt][rh * 2 + j] - mn);
                    s[nt][rh * 2 + j] = p;
                    ps += p;
                }
            }
            ps += __shfl_xor_sync(0xffffffffu, ps, 1);
            ps += __shfl_xor_sync(0xffffffffu, ps, 2);
            l2[rh] = l2[rh] * corr + ps;
#pragma unroll
            for (int nt = 0; nt < 8; nt++) {
                co[nt][rh * 2]     *= corr;
                co[nt][rh * 2 + 1] *= corr;
            }
        }

        uint32_t ph[8][2], pl[8][2];
#pragma unroll
        for (int nt = 0; nt < 8; nt++) {
            __half h0 = __float2half_rn(s[nt][0]), h1 = __float2half_rn(s[nt][1]);
            __half h2 = __float2half_rn(s[nt][2]), h3 = __float2half_rn(s[nt][3]);
            __half2 p01 = __halves2half2(h0, h1), p23 = __halves2half2(h2, h3);
            ph[nt][0] = *reinterpret_cast<uint32_t*>(&p01);
            ph[nt][1] = *reinterpret_cast<uint32_t*>(&p23);
            pl[nt][0] = h2pack(s[nt][0] - __half2float(h0), s[nt][1] - __half2float(h1));
            pl[nt][1] = h2pack(s[nt][2] - __half2float(h2), s[nt][3] - __half2float(h3));
        }

#pragma unroll
        for (int ks = 0; ks < 4; ks++) {
            uint32_t aPh[4] = { ph[2*ks][0], ph[2*ks][1], ph[2*ks+1][0], ph[2*ks+1][1] };
            uint32_t aPl[4] = { pl[2*ks][0], pl[2*ks][1], pl[2*ks+1][0], pl[2*ks+1][1] };
#pragma unroll
            for (int np = 0; np < 4; np++) {
                uint32_t vH[4], vL[4];
                LDSM4T(vH, sVh + bVOff + ks * (16 * AROW * 2) + np * 32);
                LDSM4T(vL, sVl + bVOff + ks * (16 * AROW * 2) + np * 32);
                MMAF16(co[np * 2],     aPh, vH);
                MMAF16(co[np * 2],     aPl, vH);
                MMAF16(co[np * 2],     aPh, vL);
                MMAF16(co[np * 2 + 1], aPh, vH + 2);
                MMAF16(co[np * 2 + 1], aPl, vH + 2);
                MMAF16(co[np * 2 + 1], aPh, vL + 2);
            }
        }
    }

    const int ocol0 = (h << 6) + jc0;
#pragma unroll
    for (int rh = 0; rh < 2; rh++) {
        float inv = 1.f / l2[rh];
        size_t rbase = (size_t)(b * S_ + baserow + rh * 8) * K2_;
#pragma unroll
        for (int nt = 0; nt < 8; nt++) {
            float v0 = co[nt][rh * 2]     * inv;
            float v1 = co[nt][rh * 2 + 1] * inv;
            unsigned short h0, l0, h1, l1;
            split16(v0, h0, l0);
            split16(v1, h1, l1);
            size_t p = rbase + ocol0 + nt * 8;
            *(uint32_t*)(Osplit + p)        = ((uint32_t)h1 << 16) | h0;
            *(uint32_t*)(Osplit + p + 1024) = ((uint32_t)l1 << 16) | l0;
        }
    }
}

// ---------------------------------------------------------------------------
extern "C" void kernel_launch(void* const* d_in, const int* in_sizes, int n_in,
                              void* d_out, int out_size)
{
    const float* x  = (const float*)d_in[0];
    const float* wq = (const float*)d_in[1];
    const float* bq = (const float*)d_in[2];
    const float* wk = (const float*)d_in[3];
    const float* bk = (const float*)d_in[4];
    const float* wv = (const float*)d_in[5];
    const float* bv = (const float*)d_in[6];
    const float* wo = (const float*)d_in[7];
    const float* bo = (const float*)d_in[8];
    float* out = (float*)d_out;

    __half *qh, *ql, *kh, *kl, *vh, *vl;
    unsigned short *xs, *ws, *wos, *aos;
    cudaGetSymbolAddress((void**)&qh,  g_qh);  cudaGetSymbolAddress((void**)&ql,  g_ql);
    cudaGetSymbolAddress((void**)&kh,  g_kh);  cudaGetSymbolAddress((void**)&kl,  g_kl);
    cudaGetSymbolAddress((void**)&vh,  g_vh);  cudaGetSymbolAddress((void**)&vl,  g_vl);
    cudaGetSymbolAddress((void**)&xs,  g_xs);
    cudaGetSymbolAddress((void**)&ws,  g_ws);
    cudaGetSymbolAddress((void**)&wos, g_wos);
    cudaGetSymbolAddress((void**)&aos, g_aos);

    cudaFuncSetAttribute(hgemm<0>, cudaFuncAttributeMaxDynamicSharedMemorySize, GEMM_SMEM);
    cudaFuncSetAttribute(hgemm<1>, cudaFuncAttributeMaxDynamicSharedMemorySize, GEMM_SMEM);
    cudaFuncSetAttribute(attn_mma, cudaFuncAttributeMaxDynamicSharedMemorySize, ATT_SMEM);

    // Prep: operand splits (x + all 4 weights in one launch each)
    split_x_kernel<<<(M_ * D_) / (256 * 4), 256>>>((const float4*)x, xs);
    dim3 tg(32, 32, 4), tb(32, 8);
    split_w4_kernel<<<tg, tb>>>(wq, wk, wv, wo, ws, wos);

    // Fused QKV projections -> fp16 hi/lo [B,H,S,DH] (1/sqrt(DH) folded into Q)
    dim3 gq(D_ / 128, M_ / 256, 3);   // (8, 16, 3)
    hgemm<1><<<gq, 256, GEMM_SMEM>>>(
        (const __half*)xs, (const __half*)ws,
        bq, bk, bv, nullptr,
        (unsigned short*)qh, (unsigned short*)ql,
        (unsigned short*)kh, (unsigned short*)kl,
        (unsigned short*)vh, (unsigned short*)vl);

    // Attention (HMMA, cp.async ring)
    attn_mma<<<dim3(S_ / QT_, H_, B_), 256, ATT_SMEM>>>(
        qh, ql, kh, kl, vh, vl, aos);

    // Output projection
    dim3 go(D_ / 128, M_ / 256, 1);   // (8, 16)
    hgemm<0><<<go, 256, GEMM_SMEM>>>(
        (const __half*)aos, (const __half*)wos,
        bo, bo, bo, out,
        nullptr, nullptr, nullptr, nullptr, nullptr, nullptr);
}

// round 8
// speedup vs baseline: 1.0463x; 1.0437x over previous
#include <cuda_runtime.h>
#include <cuda_bf16.h>
#include <cuda_fp16.h>
#include <math.h>
#include <cstdint>

#define B_   2
#define S_   2048
#define D_   1024
#define H_   16
#define DH_  64
#define WIN_ 256
#define M_   (B_*S_)        // 4096
#define K2_  2048           // split-GEMM K (hi | 64*lo)

// ---------------------------------------------------------------------------
// Scratch (static device globals — no allocation)
// ---------------------------------------------------------------------------
__device__ __align__(16) __half g_qh[B_*H_*S_*DH_], g_ql[B_*H_*S_*DH_];
__device__ __align__(16) __half g_kh[B_*H_*S_*DH_], g_kl[B_*H_*S_*DH_];
__device__ __align__(16) __half g_vh[B_*H_*S_*DH_], g_vl[B_*H_*S_*DH_];
__device__ __align__(16) __half g_xs [(size_t)M_*K2_];   // x split [M,2048] = [hi | 64*lo]
__device__ __align__(16) __half g_ws [(size_t)3*D_*K2_]; // wq|wk|wv split [N,2048] = [64*hi | hi]
__device__ __align__(16) __half g_wos[(size_t)D_*K2_];   // wo split
__device__ __align__(16) __half g_aos[(size_t)M_*K2_];   // attn out split

// ---------------------------------------------------------------------------
// helpers
// ---------------------------------------------------------------------------
__device__ __forceinline__ uint32_t smem_u32(const void* p) {
    uint32_t a;
    asm("{ .reg .u64 t; cvta.to.shared.u64 t, %1; cvt.u32.u64 %0, t; }"
        : "=r"(a) : "l"(p));
    return a;
}

#define CP16(sm_addr, gptr) \
    asm volatile("cp.async.cg.shared.global [%0], [%1], 16;" \
                 :: "r"(sm_addr), "l"(gptr) : "memory")
#define CP_COMMIT() asm volatile("cp.async.commit_group;" ::: "memory")

#define LDSM4(r, addr) \
    asm volatile("ldmatrix.sync.aligned.m8n8.x4.shared.b16 {%0,%1,%2,%3}, [%4];" \
        : "=r"((r)[0]), "=r"((r)[1]), "=r"((r)[2]), "=r"((r)[3]) : "r"(addr))

#define LDSM4T(r, addr) \
    asm volatile("ldmatrix.sync.aligned.m8n8.x4.trans.shared.b16 {%0,%1,%2,%3}, [%4];" \
        : "=r"((r)[0]), "=r"((r)[1]), "=r"((r)[2]), "=r"((r)[3]) : "r"(addr))

#define MMAF16(c, a, b) \
    asm volatile("mma.sync.aligned.m16n8k16.row.col.f32.f16.f16.f32 " \
        "{%0,%1,%2,%3}, {%4,%5,%6,%7}, {%8,%9}, {%0,%1,%2,%3};" \
        : "+f"((c)[0]), "+f"((c)[1]), "+f"((c)[2]), "+f"((c)[3]) \
        : "r"((a)[0]), "r"((a)[1]), "r"((a)[2]), "r"((a)[3]), \
          "r"((b)[0]), "r"((b)[1]))

__device__ __forceinline__ uint32_t h2pack(float a, float b) {
    __half2 h = __floats2half2_rn(a, b);
    return *reinterpret_cast<uint32_t*>(&h);
}

// fp16 split: value -> (hi, 64*lo)   [GEMM operand layout]
__device__ __forceinline__ void split16(float f, unsigned short& h, unsigned short& l) {
    __half hb = __float2half_rn(f);
    float r = (f - __half2float(hb)) * 64.0f;
    __half lb = __float2half_rn(r);
    h = *reinterpret_cast<unsigned short*>(&hb);
    l = *reinterpret_cast<unsigned short*>(&lb);
}

// fp16 split: value -> (hi, lo) unscaled   [attention operand layout]
__device__ __forceinline__ void split16p(float f, unsigned short& h, unsigned short& l) {
    __half hb = __float2half_rn(f);
    __half lb = __float2half_rn(f - __half2float(hb));
    h = *reinterpret_cast<unsigned short*>(&hb);
    l = *reinterpret_cast<unsigned short*>(&lb);
}

// ---------------------------------------------------------------------------
// Prep: split x into [M,2048] = [hi | 64*lo]
// ---------------------------------------------------------------------------
__global__ __launch_bounds__(256) void split_x_kernel(
    const float4* __restrict__ x, unsigned short* __restrict__ out)
{
    int i = blockIdx.x * 256 + threadIdx.x;
    int r = i >> 8;
    int c = i & 255;
    float4 f = x[i];
    ushort4 h, l;
    split16(f.x, h.x, l.x);
    split16(f.y, h.y, l.y);
    split16(f.z, h.z, l.z);
    split16(f.w, h.w, l.w);
    size_t base = (size_t)r * K2_ + (c << 2);
    *(ushort4*)(out + base)        = h;
    *(ushort4*)(out + base + 1024) = l;
}

// ---------------------------------------------------------------------------
// Prep: transpose 4 weight mats [K,N] -> [N,2048] = [64*hi | hi] in ONE launch
// ---------------------------------------------------------------------------
__global__ __launch_bounds__(256) void split_w4_kernel(
    const float* __restrict__ wq, const float* __restrict__ wk,
    const float* __restrict__ wv, const float* __restrict__ wo,
    unsigned short* __restrict__ ws, unsigned short* __restrict__ wos)
{
    const int z = blockIdx.z;
    const float* w = (z == 0) ? wq : (z == 1) ? wk : (z == 2) ? wv : wo;
    unsigned short* out = (z == 3) ? wos : ws + (size_t)z * D_ * K2_;

    __shared__ float t[32][33];
    int tx = threadIdx.x, ty = threadIdx.y;
    int n0 = blockIdx.x * 32, k0 = blockIdx.y * 32;
#pragma unroll
    for (int j = 0; j < 32; j += 8)
        t[ty + j][tx] = w[(size_t)(k0 + ty + j) * D_ + n0 + tx];
    __syncthreads();
#pragma unroll
    for (int j = 0; j < 32; j += 8) {
        float f = t[tx][ty + j];
        __half h64 = __float2half_rn(f * 64.0f);
        __half h1  = __float2half_rn(f);
        size_t o = (size_t)(n0 + ty + j) * K2_ + k0 + tx;
        out[o]        = *reinterpret_cast<unsigned short*>(&h64);
        out[o + 1024] = *reinterpret_cast<unsigned short*>(&h1);
    }
}

// ---------------------------------------------------------------------------
// HMMA GEMM: C = A'[M,2048] @ B'[N,2048]^T = 64 * (A @ Bh^T)
// CTA tile 256x128, BK=32, 4-stage cp.async pipeline, 8 warps (4x2), 64x64/warp.
// (unchanged from round 7 — measured at the legacy-HMMA rate cap)
// ---------------------------------------------------------------------------
#define BK_      32
#define NITER_   (K2_ / BK_)        // 64
#define ROW_ST   80
#define A_BYTES2 (256 * ROW_ST)     // 20480
#define B_BYTES2 (128 * ROW_ST)     // 10240
#define STG2     (A_BYTES2 + B_BYTES2)   // 30720
#define GEMM_SMEM (4 * STG2)        // 122880

template<int MODE>
__global__ __launch_bounds__(256) void hgemm(
    const __half* __restrict__ A, const __half* __restrict__ Bw,
    const float* __restrict__ b0, const float* __restrict__ b1, const float* __restrict__ b2,
    float* __restrict__ fo,
    unsigned short* __restrict__ qh, unsigned short* __restrict__ ql,
    unsigned short* __restrict__ kh, unsigned short* __restrict__ kl,
    unsigned short* __restrict__ vh, unsigned short* __restrict__ vl)
{
    extern __shared__ char smc[];
    const uint32_t sb = smem_u32(smc);
    const int tid  = threadIdx.x;
    const int lane = tid & 31;
    const int wid  = tid >> 5;
    const int wm   = wid >> 1;
    const int wn   = wid & 1;
    const int bm   = blockIdx.y << 8;
    const int bn   = blockIdx.x << 7;

    const __half* Bp;
    const float* bias;
    unsigned short *Oh, *Ol;
    float scale;
    if (MODE == 1) {
        int z = blockIdx.z;
        Bp    = Bw + (size_t)z * D_ * K2_;
        bias  = (z == 0) ? b0 : (z == 1) ? b1 : b2;
        Oh    = (z == 0) ? qh : (z == 1) ? kh : vh;
        Ol    = (z == 0) ? ql : (z == 1) ? kl : vl;
        scale = (z == 0) ? 0.125f : 1.0f;
    } else {
        Bp = Bw; bias = b0; Oh = nullptr; Ol = nullptr; scale = 1.0f;
    }
    const float cscale = scale * 0.015625f;   // scale/64

    const int lr = tid >> 2;
    const int lc = (tid & 3) << 4;
    const int gc = (tid & 3) << 3;
    auto load_stage = [&](int i) {
        const uint32_t st = sb + (i & 3) * STG2;
        const int k0 = i << 5;
#pragma unroll
        for (int h = 0; h < 4; h++) {
            int r = lr + (h << 6);
            CP16(st + r * ROW_ST + lc, A + (size_t)(bm + r) * K2_ + k0 + gc);
        }
#pragma unroll
        for (int h = 0; h < 2; h++) {
            int r = lr + (h << 6);
            CP16(st + A_BYTES2 + r * ROW_ST + lc, Bp + (size_t)(bn + r) * K2_ + k0 + gc);
        }
        CP_COMMIT();
    };

    load_stage(0); load_stage(1); load_stage(2);

    const int a_row  = lane & 15;
    const int a_koff = ((lane >> 4) << 3);
    const int b_row  = (lane & 7) + ((lane >> 4) << 3);
    const int b_koff = (((lane >> 3) & 1) << 3);
    const uint32_t aAddr = sb + (wm * 64 + a_row) * ROW_ST + a_koff * 2;
    const uint32_t bAddr = sb + A_BYTES2 + (wn * 64 + b_row) * ROW_ST + b_koff * 2;

    float c[4][8][4];
#pragma unroll
    for (int i = 0; i < 4; i++)
#pragma unroll
        for (int j = 0; j < 8; j++)
#pragma unroll
            for (int q = 0; q < 4; q++) c[i][j][q] = 0.f;

#pragma unroll 1
    for (int i = 0; i < NITER_; i++) {
        asm volatile("cp.async.wait_group 2;" ::: "memory");
        __syncthreads();
        const uint32_t so = (i & 3) * STG2;
#pragma unroll
        for (int kk = 0; kk < 2; kk++) {
            uint32_t a[4][4], b[8][2];
#pragma unroll
            for (int mt = 0; mt < 4; mt++)
                LDSM4(a[mt], aAddr + so + mt * (16 * ROW_ST) + kk * 32);
#pragma unroll
            for (int np = 0; np < 4; np++) {
                uint32_t r[4];
                LDSM4(r, bAddr + so + np * (16 * ROW_ST) + kk * 32);
                b[np * 2][0] = r[0]; b[np * 2][1] = r[1];
                b[np * 2 + 1][0] = r[2]; b[np * 2 + 1][1] = r[3];
            }
#pragma unroll
            for (int mt = 0; mt < 4; mt++)
#pragma unroll
                for (int nt = 0; nt < 8; nt++)
                    MMAF16(c[mt][nt], a[mt], b[nt]);
        }
        if (i + 3 < NITER_) load_stage(i + 3);
        else                CP_COMMIT();
    }

    const int row0 = bm + wm * 64 + (lane >> 2);
    const int col0 = bn + wn * 64 + ((lane & 3) << 1);
#pragma unroll
    for (int mt = 0; mt < 4; mt++) {
#pragma unroll
        for (int nt = 0; nt < 8; nt++) {
            int gn = col0 + nt * 8;
            float bx = bias[gn] * scale, by = bias[gn + 1] * scale;
#pragma unroll
            for (int half = 0; half < 2; half++) {
                int gm = row0 + mt * 16 + half * 8;
                float ox = c[mt][nt][half * 2 + 0] * cscale + bx;
                float oy = c[mt][nt][half * 2 + 1] * cscale + by;
                if (MODE == 0) {
                    float2 o = make_float2(ox, oy);
                    *(float2*)(fo + (size_t)gm * D_ + gn) = o;
                } else {
                    int bb = gm >> 11, ss = gm & (S_ - 1);
                    int hh = gn >> 6,  dd = gn & (DH_ - 1);
                    unsigned short h0, l0, h1, l1;
                    split16p(ox, h0, l0);
                    split16p(oy, h1, l1);
                    size_t addr = ((((size_t)bb * H_ + hh) * S_ + ss) << 6) + dd;
                    *(uint32_t*)(Oh + addr) = ((uint32_t)h1 << 16) | h0;
                    *(uint32_t*)(Ol + addr) = ((uint32_t)l1 << 16) | l0;
                }
            }
        }
    }
}

// ---------------------------------------------------------------------------
// HMMA windowed attention v3: 2-buffer K/V ring (smem 110592 -> 2 CTAs/SM).
// Pipeline order per chunk: wait_group 0 -> syncthreads -> issue load(ci+1)
// -> compute(ci).  The barrier precedes the load, so overwriting the buffer
// consumed at ci-1 is race-free; compute(ci) overlaps the in-flight load.
// block = (128 q-rows, head, batch), 8 warps, warp = 16 q-rows x 64-key chunk.
// ---------------------------------------------------------------------------
#define AROW    72                     // halfs per smem row (144 B)
#define QT_     128
#define QBYTES  (2 * 128 * AROW * 2)   // Qh+Ql: 36864
#define KVSTG   (4 * 64 * AROW * 2)    // Kh,Kl,Vh,Vl: 36864
#define ATT_SMEM (QBYTES + 2 * KVSTG)  // 110592 -> 2 CTAs/SM

__global__ __launch_bounds__(256) void attn_mma(
    const __half* __restrict__ Qh_g, const __half* __restrict__ Ql_g,
    const __half* __restrict__ Kh_g, const __half* __restrict__ Kl_g,
    const __half* __restrict__ Vh_g, const __half* __restrict__ Vl_g,
    unsigned short* __restrict__ Osplit)
{
    extern __shared__ char sma[];
    const uint32_t sQ  = smem_u32(sma);
    const uint32_t sKV = sQ + QBYTES;

    const int tid  = threadIdx.x;
    const int lane = tid & 31;
    const int w    = tid >> 5;
    const int q0t  = blockIdx.x << 7;
    const int h    = blockIdx.y;
    const int b    = blockIdx.z;
    const size_t bh = ((size_t)b * H_ + h) * S_;

    const int kstart = (q0t - WIN_) > 0 ? (q0t - WIN_) : 0;
    const int nch    = ((q0t + 64) - kstart) / 64 + 1;

    auto load_q = [&]() {
        const __half* srcs[2] = { Qh_g + (bh + q0t) * DH_, Ql_g + (bh + q0t) * DH_ };
#pragma unroll
        for (int it = 0; it < 8; it++) {
            int i = it * 256 + tid;
            int arr = i >> 10, rem = i & 1023;
            int row = rem >> 3, c = rem & 7;
            CP16(sQ + arr * (128 * AROW * 2) + row * (AROW * 2) + c * 16,
                 srcs[arr] + (row << 6) + (c << 3));
        }
    };
    auto load_kv = [&](int kb, int buf) {
        const __half* srcs[4] = { Kh_g + (bh + kb) * DH_, Kl_g + (bh + kb) * DH_,
                                  Vh_g + (bh + kb) * DH_, Vl_g + (bh + kb) * DH_ };
        const uint32_t base = sKV + buf * KVSTG;
#pragma unroll
        for (int it = 0; it < 8; it++) {
            int i = it * 256 + tid;
            int arr = i >> 9, rem = i & 511;
            int row = rem >> 3, c = rem & 7;
            CP16(base + arr * (64 * AROW * 2) + row * (AROW * 2) + c * 16,
                 srcs[arr] + (row << 6) + (c << 3));
        }
    };

    // prologue: Q + KV chunk 0 in one group
    load_q();
    load_kv(kstart, 0);
    CP_COMMIT();

    const uint32_t aOff  = (w * 16 + (lane & 15)) * (AROW * 2) + ((lane >> 4) << 4);
    const uint32_t bKOff = ((lane & 7) + ((lane >> 4) << 3)) * (AROW * 2)
                         + (((lane >> 3) & 1) << 4);
    const uint32_t bVOff = ((lane & 7) + (((lane >> 3) & 1) << 3)) * (AROW * 2)
                         + ((lane >> 4) << 4);
    const uint32_t sQh = sQ, sQl = sQ + 128 * AROW * 2;

    float m2[2] = {-1e30f, -1e30f};
    float l2[2] = {0.f, 0.f};
    float co[8][4];
#pragma unroll
    for (int i = 0; i < 8; i++)
#pragma unroll
        for (int j = 0; j < 4; j++) co[i][j] = 0.f;

    const int baserow = q0t + w * 16 + (lane >> 2);
    const int jc0     = (lane & 3) << 1;
    const int qmin    = q0t + w * 16;

#pragma unroll 1
    for (int ci = 0; ci < nch; ci++) {
        const int kb = kstart + ci * 64;
        asm volatile("cp.async.wait_group 0;" ::: "memory");   // load(ci) done
        __syncthreads();                                       // all warps past compute(ci-1)
        if (ci + 1 < nch) { load_kv(kstart + (ci + 1) * 64, (ci + 1) & 1); CP_COMMIT(); }

        if (kb > qmin + 15 || kb + 63 < qmin - WIN_) continue;

        const uint32_t kvb = sKV + (ci & 1) * KVSTG;
        const uint32_t sKh = kvb;
        const uint32_t sKl = kvb + (64 * AROW * 2);
        const uint32_t sVh = kvb + 2 * (64 * AROW * 2);
        const uint32_t sVl = kvb + 3 * (64 * AROW * 2);

        float s[8][4];
#pragma unroll
        for (int i = 0; i < 8; i++)
#pragma unroll
            for (int j = 0; j < 4; j++) s[i][j] = 0.f;

#pragma unroll
        for (int ks = 0; ks < 4; ks++) {
            uint32_t aH[4], aL[4];
            LDSM4(aH, sQh + aOff + ks * 32);
            LDSM4(aL, sQl + aOff + ks * 32);
#pragma unroll
            for (int np = 0; np < 4; np++) {
                uint32_t bH[4], bL[4];
                LDSM4(bH, sKh + bKOff + np * (16 * AROW * 2) + ks * 32);
                LDSM4(bL, sKl + bKOff + np * (16 * AROW * 2) + ks * 32);
                MMAF16(s[np * 2],     aH, bH);
                MMAF16(s[np * 2],     aL, bH);
                MMAF16(s[np * 2],     aH, bL);
                MMAF16(s[np * 2 + 1], aH, bH + 2);
                MMAF16(s[np * 2 + 1], aL, bH + 2);
                MMAF16(s[np * 2 + 1], aH, bL + 2);
            }
        }

#pragma unroll
        for (int rh = 0; rh < 2; rh++) {
            int qi = baserow + rh * 8;
            float mx = -1e30f;
#pragma unroll
            for (int nt = 0; nt < 8; nt++) {
#pragma unroll
                for (int j = 0; j < 2; j++) {
                    int kj = kb + nt * 8 + jc0 + j;
                    float& v = s[nt][rh * 2 + j];
                    if (kj > qi || (qi - kj) > WIN_) v = -1e30f;
                    mx = fmaxf(mx, v);
                }
            }
            mx = fmaxf(mx, __shfl_xor_sync(0xffffffffu, mx, 1));
            mx = fmaxf(mx, __shfl_xor_sync(0xffffffffu, mx, 2));
            float mn   = fmaxf(m2[rh], mx);
            float corr = __expf(m2[rh] - mn);
            m2[rh] = mn;
            float ps = 0.f;
#pragma unroll
            for (int nt = 0; nt < 8; nt++) {
#pragma unroll
                for (int j = 0; j < 2; j++) {
                    float p = __expf(s[nt][rh * 2 + j] - mn);
                    s[nt][rh * 2 + j] = p;
                    ps += p;
                }
            }
            ps += __shfl_xor_sync(0xffffffffu, ps, 1);
            ps += __shfl_xor_sync(0xffffffffu, ps, 2);
            l2[rh] = l2[rh] * corr + ps;
#pragma unroll
            for (int nt = 0; nt < 8; nt++) {
                co[nt][rh * 2]     *= corr;
                co[nt][rh * 2 + 1] *= corr;
            }
        }

        uint32_t ph[8][2], pl[8][2];
#pragma unroll
        for (int nt = 0; nt < 8; nt++) {
            __half h0 = __float2half_rn(s[nt][0]), h1 = __float2half_rn(s[nt][1]);
            __half h2 = __float2half_rn(s[nt][2]), h3 = __float2half_rn(s[nt][3]);
            __half2 p01 = __halves2half2(h0, h1), p23 = __halves2half2(h2, h3);
            ph[nt][0] = *reinterpret_cast<uint32_t*>(&p01);
            ph[nt][1] = *reinterpret_cast<uint32_t*>(&p23);
            pl[nt][0] = h2pack(s[nt][0] - __half2float(h0), s[nt][1] - __half2float(h1));
            pl[nt][1] = h2pack(s[nt][2] - __half2float(h2), s[nt][3] - __half2float(h3));
        }

#pragma unroll
        for (int ks = 0; ks < 4; ks++) {
            uint32_t aPh[4] = { ph[2*ks][0], ph[2*ks][1], ph[2*ks+1][0], ph[2*ks+1][1] };
            uint32_t aPl[4] = { pl[2*ks][0], pl[2*ks][1], pl[2*ks+1][0], pl[2*ks+1][1] };
#pragma unroll
            for (int np = 0; np < 4; np++) {
                uint32_t vH[4], vL[4];
                LDSM4T(vH, sVh + bVOff + ks * (16 * AROW * 2) + np * 32);
                LDSM4T(vL, sVl + bVOff + ks * (16 * AROW * 2) + np * 32);
                MMAF16(co[np * 2],     aPh, vH);
                MMAF16(co[np * 2],     aPl, vH);
                MMAF16(co[np * 2],     aPh, vL);
                MMAF16(co[np * 2 + 1], aPh, vH + 2);
                MMAF16(co[np * 2 + 1], aPl, vH + 2);
                MMAF16(co[np * 2 + 1], aPh, vL + 2);
            }
        }
    }

    const int ocol0 = (h << 6) + jc0;
#pragma unroll
    for (int rh = 0; rh < 2; rh++) {
        float inv = 1.f / l2[rh];
        size_t rbase = (size_t)(b * S_ + baserow + rh * 8) * K2_;
#pragma unroll
        for (int nt = 0; nt < 8; nt++) {
            float v0 = co[nt][rh * 2]     * inv;
            float v1 = co[nt][rh * 2 + 1] * inv;
            unsigned short h0, l0, h1, l1;
            split16(v0, h0, l0);
            split16(v1, h1, l1);
            size_t p = rbase + ocol0 + nt * 8;
            *(uint32_t*)(Osplit + p)        = ((uint32_t)h1 << 16) | h0;
            *(uint32_t*)(Osplit + p + 1024) = ((uint32_t)l1 << 16) | l0;
        }
    }
}

// ---------------------------------------------------------------------------
extern "C" void kernel_launch(void* const* d_in, const int* in_sizes, int n_in,
                              void* d_out, int out_size)
{
    const float* x  = (const float*)d_in[0];
    const float* wq = (const float*)d_in[1];
    const float* bq = (const float*)d_in[2];
    const float* wk = (const float*)d_in[3];
    const float* bk = (const float*)d_in[4];
    const float* wv = (const float*)d_in[5];
    const float* bv = (const float*)d_in[6];
    const float* wo = (const float*)d_in[7];
    const float* bo = (const float*)d_in[8];
    float* out = (float*)d_out;

    __half *qh, *ql, *kh, *kl, *vh, *vl;
    unsigned short *xs, *ws, *wos, *aos;
    cudaGetSymbolAddress((void**)&qh,  g_qh);  cudaGetSymbolAddress((void**)&ql,  g_ql);
    cudaGetSymbolAddress((void**)&kh,  g_kh);  cudaGetSymbolAddress((void**)&kl,  g_kl);
    cudaGetSymbolAddress((void**)&vh,  g_vh);  cudaGetSymbolAddress((void**)&vl,  g_vl);
    cudaGetSymbolAddress((void**)&xs,  g_xs);
    cudaGetSymbolAddress((void**)&ws,  g_ws);
    cudaGetSymbolAddress((void**)&wos, g_wos);
    cudaGetSymbolAddress((void**)&aos, g_aos);

    cudaFuncSetAttribute(hgemm<0>, cudaFuncAttributeMaxDynamicSharedMemorySize, GEMM_SMEM);
    cudaFuncSetAttribute(hgemm<1>, cudaFuncAttributeMaxDynamicSharedMemorySize, GEMM_SMEM);
    cudaFuncSetAttribute(attn_mma, cudaFuncAttributeMaxDynamicSharedMemorySize, ATT_SMEM);

    // Prep: operand splits
    split_x_kernel<<<(M_ * D_) / (256 * 4), 256>>>((const float4*)x, xs);
    dim3 tg(32, 32, 4), tb(32, 8);
    split_w4_kernel<<<tg, tb>>>(wq, wk, wv, wo, ws, wos);

    // Fused QKV projections -> fp16 hi/lo [B,H,S,DH] (1/sqrt(DH) folded into Q)
    dim3 gq(D_ / 128, M_ / 256, 3);
    hgemm<1><<<gq, 256, GEMM_SMEM>>>(
        (const __half*)xs, (const __half*)ws,
        bq, bk, bv, nullptr,
        (unsigned short*)qh, (unsigned short*)ql,
        (unsigned short*)kh, (unsigned short*)kl,
        (unsigned short*)vh, (unsigned short*)vl);

    // Attention (HMMA, 2-buffer ring, 2 CTAs/SM)
    attn_mma<<<dim3(S_ / QT_, H_, B_), 256, ATT_SMEM>>>(
        qh, ql, kh, kl, vh, vl, aos);

    // Output projection
    dim3 go(D_ / 128, M_ / 256, 1);
    hgemm<0><<<go, 256, GEMM_SMEM>>>(
        (const __half*)aos, (const __half*)wos,
        bo, bo, bo, out,
        nullptr, nullptr, nullptr, nullptr, nullptr, nullptr);
}